// round 2
// baseline (speedup 1.0000x reference)
#include <cuda_runtime.h>
#include <cuda_bf16.h>

// Exclusive-prefix starts of each graph, computed on device (no cudaMalloc allowed).
__device__ int g_starts[4096];

// Single-block Hillis-Steele inclusive scan -> exclusive starts.
// blockDim.x must be >= b and a power of two (we launch 1024).
__global__ void cdba_scan_kernel(const int* __restrict__ len, int b) {
    __shared__ int s[1024];
    int t = threadIdx.x;
    int v = (t < b) ? len[t] : 0;
    s[t] = v;
    __syncthreads();
    #pragma unroll
    for (int off = 1; off < 1024; off <<= 1) {
        int x = (t >= off) ? s[t - off] : 0;
        __syncthreads();
        s[t] += x;
        __syncthreads();
    }
    if (t < b) g_starts[t] = s[t] - v;   // exclusive cumsum
}

// Gather formulation: each thread produces one float4 of the padded output.
// out[b][slot][:] = attr[starts[b]+slot][:] if slot < len[b] else 0
__global__ void __launch_bounds__(256)
cdba_gather_kernel(const float4* __restrict__ attr,
                   const int*    __restrict__ len,
                   float4*       __restrict__ out,
                   int rowF4,      // F/4 (64)
                   int maxlen,     // MAX_LEN (1024)
                   long long totalF4)
{
    long long i = (long long)blockIdx.x * blockDim.x + threadIdx.x;
    if (i >= totalF4) return;

    int        col  = (int)(i % rowF4);
    long long  row  = i / rowF4;
    int        bid  = (int)(row / maxlen);
    int        slot = (int)(row % maxlen);

    int L = __ldg(&len[bid]);          // warp-uniform broadcast
    float4 v = make_float4(0.f, 0.f, 0.f, 0.f);
    if (slot < L) {
        long long src = (long long)(g_starts[bid] + slot) * rowF4 + col;
        v = __ldcs(&attr[src]);        // streaming read (no L2 reuse)
    }
    __stcs(&out[i], v);                // streaming write (write-once)
}

extern "C" void kernel_launch(void* const* d_in, const int* in_sizes, int n_in,
                              void* d_out, int out_size) {
    // metadata order: attr (f32, N*F), graph_id_attr (i32, N), attr_len (i32, B)
    const float* attr = (const float*)d_in[0];
    const int*   alen = (const int*)  d_in[2];

    int n_nodes  = in_sizes[1];                 // N (count of graph_id entries)
    int b        = in_sizes[2];                 // B
    int f        = in_sizes[0] / n_nodes;       // F (256)
    int rowF4    = f / 4;                       // 64
    int maxlen   = out_size / (b * f);          // 1024

    cdba_scan_kernel<<<1, 1024>>>(alen, b);

    long long totalF4 = (long long)out_size / 4;
    int threads = 256;
    long long blocks = (totalF4 + threads - 1) / threads;
    cdba_gather_kernel<<<(unsigned)blocks, threads>>>(
        (const float4*)attr, alen, (float4*)d_out, rowF4, maxlen, totalF4);
}

// round 3
// speedup vs baseline: 1.1029x; 1.1029x over previous
#include <cuda_runtime.h>
#include <cuda_bf16.h>

// Exclusive-prefix starts of each graph (no cudaMalloc allowed -> device global).
__device__ int g_starts[4096];

// Single-block Hillis-Steele inclusive scan -> exclusive starts.
__global__ void cdba_scan_kernel(const int* __restrict__ len, int b) {
    __shared__ int s[1024];
    int t = threadIdx.x;
    int v = (t < b) ? len[t] : 0;
    s[t] = v;
    __syncthreads();
    #pragma unroll
    for (int off = 1; off < 1024; off <<= 1) {
        int x = (t >= off) ? s[t - off] : 0;
        __syncthreads();
        s[t] += x;
        __syncthreads();
    }
    if (t < b) g_starts[t] = s[t] - v;   // exclusive cumsum
}

// Gather formulation, zero div/mod:
//   block = (rowF4=64, 4), grid = (maxlen/16, B)
//   Each thread emits 4 float4 output elements (4 slots, same column).
#define CDBA_SLOT_Y 4
#define CDBA_ITEMS  4
__global__ void __launch_bounds__(256)
cdba_gather_kernel(const float4* __restrict__ attr,
                   const int*    __restrict__ len,
                   float4*       __restrict__ out,
                   int rowF4,      // F/4 (64)
                   int maxlen)     // MAX_LEN (1024)
{
    const int col   = threadIdx.x;                               // 0..63
    const int bid   = blockIdx.y;                                // graph id
    const int slot0 = blockIdx.x * (CDBA_SLOT_Y * CDBA_ITEMS) + threadIdx.y;

    const int L     = __ldg(&len[bid]);      // warp-uniform
    const int start = g_starts[bid];         // warp-uniform

    const long long outBase = ((long long)bid * maxlen) * rowF4 + col;
    const long long srcBase = (long long)start * rowF4 + col;

    float4 v[CDBA_ITEMS];
    #pragma unroll
    for (int k = 0; k < CDBA_ITEMS; k++) {
        int slot = slot0 + k * CDBA_SLOT_Y;
        v[k] = make_float4(0.f, 0.f, 0.f, 0.f);
        if (slot < L)
            v[k] = __ldcs(&attr[srcBase + (long long)slot * rowF4]);  // streaming read
    }
    #pragma unroll
    for (int k = 0; k < CDBA_ITEMS; k++) {
        int slot = slot0 + k * CDBA_SLOT_Y;
        __stcs(&out[outBase + (long long)slot * rowF4], v[k]);        // streaming write
    }
}

extern "C" void kernel_launch(void* const* d_in, const int* in_sizes, int n_in,
                              void* d_out, int out_size) {
    // metadata order: attr (f32, N*F), graph_id_attr (i32, N), attr_len (i32, B)
    const float* attr = (const float*)d_in[0];
    const int*   alen = (const int*)  d_in[2];

    int n_nodes  = in_sizes[1];                 // N
    int b        = in_sizes[2];                 // B
    int f        = in_sizes[0] / n_nodes;       // F (256)
    int rowF4    = f / 4;                       // 64
    int maxlen   = out_size / (b * f);          // 1024

    cdba_scan_kernel<<<1, 1024>>>(alen, b);

    dim3 block(rowF4, CDBA_SLOT_Y);                       // 64 x 4 = 256 threads
    dim3 grid(maxlen / (CDBA_SLOT_Y * CDBA_ITEMS), b);    // (64, 256)
    cdba_gather_kernel<<<grid, block>>>(
        (const float4*)attr, alen, (float4*)d_out, rowF4, maxlen);
}

// round 5
// speedup vs baseline: 1.1276x; 1.0224x over previous
#include <cuda_runtime.h>
#include <cuda_bf16.h>

// Fused gather: single kernel, no separate scan launch.
//   block = (rowF4=64, SLOT_Y=4) = 256 threads
//   grid  = (maxlen / (SLOT_Y*ITEMS), B)
// Each block redundantly computes starts[bid] with one warp-reduce over the
// tiny (B ints, L1-resident) length array — cheaper than a serialized scan
// kernel + launch gap.
#define CDBA_SLOT_Y 4
#define CDBA_ITEMS  8

__global__ void __launch_bounds__(256)
cdba_fused_kernel(const float4* __restrict__ attr,
                  const int*    __restrict__ len,
                  float4*       __restrict__ out,
                  int rowF4,      // F/4 (64)
                  int maxlen)     // MAX_LEN (1024)
{
    const int col  = threadIdx.x;                       // 0..63
    const int bid  = blockIdx.y;                        // graph id
    const int tid  = threadIdx.x + threadIdx.y * blockDim.x;
    const int lane = tid & 31;

    // Per-warp exclusive prefix: start = sum_{j < bid} len[j].
    int s = 0;
    for (int j = lane; j < bid; j += 32)
        s += __ldg(&len[j]);
    #pragma unroll
    for (int off = 16; off > 0; off >>= 1)
        s += __shfl_xor_sync(0xffffffffu, s, off);
    const int start = s;                                // warp-uniform
    const int L     = __ldg(&len[bid]);                 // warp-uniform

    const int slot0 = blockIdx.x * (CDBA_SLOT_Y * CDBA_ITEMS) + threadIdx.y;

    const long long outBase = ((long long)bid * maxlen) * rowF4 + col;
    const long long srcBase = (long long)start * rowF4 + col;

    float4 v[CDBA_ITEMS];
    #pragma unroll
    for (int k = 0; k < CDBA_ITEMS; k++) {
        int slot = slot0 + k * CDBA_SLOT_Y;
        v[k] = make_float4(0.f, 0.f, 0.f, 0.f);
        if (slot < L)
            v[k] = __ldcs(&attr[srcBase + (long long)slot * rowF4]);  // streaming read
    }
    #pragma unroll
    for (int k = 0; k < CDBA_ITEMS; k++) {
        int slot = slot0 + k * CDBA_SLOT_Y;
        if (slot < maxlen)
            __stcs(&out[outBase + (long long)slot * rowF4], v[k]);    // streaming write
    }
}

extern "C" void kernel_launch(void* const* d_in, const int* in_sizes, int n_in,
                              void* d_out, int out_size) {
    // metadata order: attr (f32, N*F), graph_id_attr (i32, N), attr_len (i32, B)
    const float* attr = (const float*)d_in[0];
    const int*   alen = (const int*)  d_in[2];

    int n_nodes  = in_sizes[1];                 // N
    int b        = in_sizes[2];                 // B
    int f        = in_sizes[0] / n_nodes;       // F (256)
    int rowF4    = f / 4;                       // 64
    int maxlen   = out_size / (b * f);          // 1024

    dim3 block(rowF4, CDBA_SLOT_Y);                                       // 256 threads
    int slotsPerBlock = CDBA_SLOT_Y * CDBA_ITEMS;                         // 32
    dim3 grid((maxlen + slotsPerBlock - 1) / slotsPerBlock, b);           // (32, 256)
    cdba_fused_kernel<<<grid, block>>>(
        (const float4*)attr, alen, (float4*)d_out, rowF4, maxlen);
}

// round 11
// speedup vs baseline: 1.1323x; 1.0041x over previous
#include <cuda_runtime.h>
#include <cuda_bf16.h>

// Fused gather, occupancy-tuned:
//   block = (rowF4=64, SLOT_Y=4) = 256 threads
//   grid  = (maxlen/(SLOT_Y*ITEMS), B) = (64, 256)
// Warp 0 computes starts[bid] (reduce over the 1KB, L1-hot length array),
// broadcasts via shared; all offsets are 32-bit (out has <2^31 float4 elems).
#define CDBA_SLOT_Y 4
#define CDBA_ITEMS  4

__global__ void __launch_bounds__(256)
cdba_fused_kernel(const float4* __restrict__ attr,
                  const int*    __restrict__ len,
                  float4*       __restrict__ out,
                  int rowF4,      // F/4 (64)
                  int maxlen)     // MAX_LEN (1024)
{
    __shared__ int s_start, s_len;

    const int col = threadIdx.x;                         // 0..63
    const int bid = blockIdx.y;                          // graph id
    const int tid = threadIdx.x + threadIdx.y * blockDim.x;

    if (tid < 32) {
        // Exclusive prefix: start = sum_{j<bid} len[j]; one warp only.
        int s = 0;
        for (int j = tid; j < bid; j += 32)
            s += __ldg(&len[j]);
        #pragma unroll
        for (int off = 16; off > 0; off >>= 1)
            s += __shfl_xor_sync(0xffffffffu, s, off);
        if (tid == 0) {
            s_start = s;
            s_len   = __ldg(&len[bid]);
        }
    }
    __syncthreads();
    const int start = s_start;
    const int L     = s_len;

    const int slot0 = blockIdx.x * (CDBA_SLOT_Y * CDBA_ITEMS) + threadIdx.y;

    // 32-bit offsets: max out index = B*MAX_LEN*rowF4 = 16.7M < 2^31.
    const unsigned outBase = ((unsigned)bid * (unsigned)maxlen) * (unsigned)rowF4
                             + (unsigned)col;
    const unsigned srcBase = (unsigned)start * (unsigned)rowF4 + (unsigned)col;

    float4 v[CDBA_ITEMS];
    #pragma unroll
    for (int k = 0; k < CDBA_ITEMS; k++) {
        int slot = slot0 + k * CDBA_SLOT_Y;
        v[k] = make_float4(0.f, 0.f, 0.f, 0.f);
        if (slot < L)
            v[k] = __ldcs(&attr[srcBase + (unsigned)slot * (unsigned)rowF4]);
    }
    #pragma unroll
    for (int k = 0; k < CDBA_ITEMS; k++) {
        int slot = slot0 + k * CDBA_SLOT_Y;
        __stcs(&out[outBase + (unsigned)slot * (unsigned)rowF4], v[k]);
    }
}

extern "C" void kernel_launch(void* const* d_in, const int* in_sizes, int n_in,
                              void* d_out, int out_size) {
    // metadata order: attr (f32, N*F), graph_id_attr (i32, N), attr_len (i32, B)
    const float* attr = (const float*)d_in[0];
    const int*   alen = (const int*)  d_in[2];

    int n_nodes  = in_sizes[1];                 // N
    int b        = in_sizes[2];                 // B
    int f        = in_sizes[0] / n_nodes;       // F (256)
    int rowF4    = f / 4;                       // 64
    int maxlen   = out_size / (b * f);          // 1024

    dim3 block(rowF4, CDBA_SLOT_Y);                                    // 256 threads
    int slotsPerBlock = CDBA_SLOT_Y * CDBA_ITEMS;                      // 16
    dim3 grid((maxlen + slotsPerBlock - 1) / slotsPerBlock, b);        // (64, 256)
    cdba_fused_kernel<<<grid, block>>>(
        (const float4*)attr, alen, (float4*)d_out, rowF4, maxlen);
}

// round 13
// speedup vs baseline: 1.1375x; 1.0046x over previous
#include <cuda_runtime.h>
#include <cuda_bf16.h>

// Fused gather with 256-bit (v8.f32) global accesses (sm_100+ LDG.E.256/STG.E.256).
//   block = (32, 8) = 256 threads; one warp = one full 1024B output row.
//   ITEMS = 2 slots per thread -> 16 slots per block; grid = (maxlen/16, B).
// Warp 0 computes starts[bid] (reduce over the 1KB L1-hot length array) and
// broadcasts via shared. All offsets 32-bit.
#define CDBA_WARPS  8
#define CDBA_ITEMS  2

__device__ __forceinline__ void ldg256_cs(const float* p, float* v) {
    asm volatile("ld.global.cs.v8.f32 {%0,%1,%2,%3,%4,%5,%6,%7}, [%8];"
        : "=f"(v[0]), "=f"(v[1]), "=f"(v[2]), "=f"(v[3]),
          "=f"(v[4]), "=f"(v[5]), "=f"(v[6]), "=f"(v[7])
        : "l"(p));
}

__device__ __forceinline__ void stg256_cs(float* p, const float* v) {
    asm volatile("st.global.cs.v8.f32 [%0], {%1,%2,%3,%4,%5,%6,%7,%8};"
        :: "l"(p),
           "f"(v[0]), "f"(v[1]), "f"(v[2]), "f"(v[3]),
           "f"(v[4]), "f"(v[5]), "f"(v[6]), "f"(v[7])
        : "memory");
}

__global__ void __launch_bounds__(256)
cdba_fused_kernel(const float* __restrict__ attr,
                  const int*   __restrict__ len,
                  float*       __restrict__ out,
                  int rowF8,      // F/8 (32)
                  int maxlen)     // MAX_LEN (1024)
{
    __shared__ int s_start, s_len;

    const int col = threadIdx.x;                         // 0..31 (float8 column)
    const int bid = blockIdx.y;                          // graph id
    const int tid = threadIdx.x + threadIdx.y * blockDim.x;

    if (tid < 32) {
        // Exclusive prefix: start = sum_{j<bid} len[j]; one warp only.
        int s = 0;
        for (int j = tid; j < bid; j += 32)
            s += __ldg(&len[j]);
        #pragma unroll
        for (int off = 16; off > 0; off >>= 1)
            s += __shfl_xor_sync(0xffffffffu, s, off);
        if (tid == 0) {
            s_start = s;
            s_len   = __ldg(&len[bid]);
        }
    }
    __syncthreads();
    const int start = s_start;
    const int L     = s_len;

    const int slot0 = blockIdx.x * (CDBA_WARPS * CDBA_ITEMS) + threadIdx.y;

    // 32-bit float8-granule offsets: max = B*MAX_LEN*rowF8 = 8.4M < 2^31.
    const unsigned outBase = ((unsigned)bid * (unsigned)maxlen) * (unsigned)rowF8
                             + (unsigned)col;
    const unsigned srcBase = (unsigned)start * (unsigned)rowF8 + (unsigned)col;

    float v[CDBA_ITEMS][8];
    #pragma unroll
    for (int k = 0; k < CDBA_ITEMS; k++) {
        int slot = slot0 + k * CDBA_WARPS;
        if (slot < L) {
            ldg256_cs(attr + 8u * (srcBase + (unsigned)slot * (unsigned)rowF8), v[k]);
        } else {
            #pragma unroll
            for (int j = 0; j < 8; j++) v[k][j] = 0.f;
        }
    }
    #pragma unroll
    for (int k = 0; k < CDBA_ITEMS; k++) {
        int slot = slot0 + k * CDBA_WARPS;
        stg256_cs(out + 8u * (outBase + (unsigned)slot * (unsigned)rowF8), v[k]);
    }
}

extern "C" void kernel_launch(void* const* d_in, const int* in_sizes, int n_in,
                              void* d_out, int out_size) {
    // metadata order: attr (f32, N*F), graph_id_attr (i32, N), attr_len (i32, B)
    const float* attr = (const float*)d_in[0];
    const int*   alen = (const int*)  d_in[2];

    int n_nodes  = in_sizes[1];                 // N
    int b        = in_sizes[2];                 // B
    int f        = in_sizes[0] / n_nodes;       // F (256)
    int rowF8    = f / 8;                       // 32
    int maxlen   = out_size / (b * f);          // 1024

    dim3 block(32, CDBA_WARPS);                                        // 256 threads
    int slotsPerBlock = CDBA_WARPS * CDBA_ITEMS;                       // 16
    dim3 grid((maxlen + slotsPerBlock - 1) / slotsPerBlock, b);        // (64, 256)
    cdba_fused_kernel<<<grid, block>>>(
        attr, alen, (float*)d_out, rowF8, maxlen);
}